// round 13
// baseline (speedup 1.0000x reference)
#include <cuda_runtime.h>

// HONU degree-3: out[r] = sum_{a<=b<=c} w(a,b,c) * xs[a][r]*xs[b][r]*xs[c][r]
// xs[0][r]=1 (bias). Weight index = lexicographic rank (closed form); the
// comb_idx input is redundant and ignored.
//
// Pair factorization: s_ab[r] = sum_c w_abc * xs[c][r];
//                     out[r] += xs[a][r]*xs[b][r]*s_ab[r].
// FOUR 'a'-streams share each xs[c] LDS.128; warp owns all 256 rows (8 rows/
// thread = 4x packed fma.rn.f32x2). NEW vs R10: weights are staged through
// smem by the warp cooperatively (lane l loads stream l&3, step l>>2; one LDG
// per 8 c-steps instead of 4 uniform LDGs per step), double-buffered so the
// L2 latency is covered by a full group of compute. Inner loop reads all 4
// streams' weights with ONE broadcast LDS.128.
// Grid=148 (1 wave), 512 thr. Cross-block reduction fused via atomic ticket.

#define NFEAT 129
#define NROW  256
#define NBLK  148
#define WPB   16
#define NRANGE (NBLK * WPB)   // 2368 ranges, one warp each (full 256 rows)

__host__ __device__ __forceinline__ int c2i(int v) { return v * (v - 1) / 2; }
__host__ __device__ __forceinline__ int c3i(int v) { return v * (v - 1) * (v - 2) / 6; }

// flat lexicographic rank of combo (a, b, b); total combos = C(131,3) = 366145
__device__ __forceinline__ int comb_base(int a, int b) {
    return 366145 - c3i(131 - a) + c2i(130 - a) - c2i(130 - b);
}

// total c-steps over all (b, quartet) rows: sum_b (b/4+1)*(129-b)
constexpr int t4_calc() {
    int t = 0;
    for (int b = 0; b < NFEAT; b++) t += (b / 4 + 1) * (NFEAT - b);
    return t;
}
constexpr int T4 = t4_calc();

__device__ float g_partial[NBLK * NROW];
__device__ int   g_count = 0;

__device__ __forceinline__ unsigned long long pack2(float w) {
    unsigned long long r;
    unsigned int wi = __float_as_uint(w);
    asm("mov.b64 %0, {%1, %1};" : "=l"(r) : "r"(wi));
    return r;
}
__device__ __forceinline__ void fma2(unsigned long long& d, unsigned long long a,
                                     unsigned long long b) {
    asm("fma.rn.f32x2 %0, %1, %2, %0;" : "+l"(d) : "l"(a), "l"(b));
}
__device__ __forceinline__ unsigned long long mul2(unsigned long long a,
                                                   unsigned long long b) {
    unsigned long long d;
    asm("mul.rn.f32x2 %0, %1, %2;" : "=l"(d) : "l"(a), "l"(b));
    return d;
}

__global__ void __launch_bounds__(512, 1)
honu_main(const float* __restrict__ x, const float* __restrict__ w,
          float* __restrict__ out) {
    extern __shared__ float smem[];
    float* xs   = smem;                   // [129][256] feature-major
    float* obuf = smem + NFEAT * NROW;    // [16][256] per-warp partials
    float* wst  = obuf + WPB * NROW;      // [16][2][32] staged weights
    __shared__ int sP4[130];
    __shared__ int is_last;

    int tid = threadIdx.x;

    // ---- prefix table ----
    if (tid < 130) {
        int p = 0;
        for (int bb = 0; bb < tid && bb < NFEAT; bb++)
            p += (bb / 4 + 1) * (NFEAT - bb);
        sP4[tid] = p;                     // sP4[129] == T4
    }

    // ---- x transposed into smem (both 256-thread halves do 64 features) ----
    {
        int r = tid & 255, h = tid >> 8;
        const float4* xg = (const float4*)(x + (size_t)r * 128 + h * 64);
#pragma unroll
        for (int k = 0; k < 16; k++) {
            float4 v = xg[k];
            int f = h * 64 + 4 * k;
            xs[(f + 1) * NROW + r] = v.x;
            xs[(f + 2) * NROW + r] = v.y;
            xs[(f + 3) * NROW + r] = v.z;
            xs[(f + 4) * NROW + r] = v.w;
        }
        if (h == 0) xs[r] = 1.0f;         // bias feature
    }
    __syncthreads();

    int warp = tid >> 5, lane = tid & 31;
    int range = blockIdx.x * WPB + warp;
    int st = lane & 3;                    // staging: stream this lane loads
    int u8 = lane >> 2;                   // staging: group-local step (0..7)
    float* wsw = wst + warp * 64;         // this warp's 2x32-float buffers

    int s = (int)(((long long)T4 * range) / NRANGE);
    int e = (int)(((long long)T4 * (range + 1)) / NRANGE);

    // ---- decode start -> (b, quartet o, c-offset) via binary search ----
    int lo = 0, hi = NFEAT - 1;
    while (lo < hi) {                     // largest b with sP4[b] <= s
        int mid = (lo + hi + 1) >> 1;
        if (sP4[mid] <= s) lo = mid; else hi = mid - 1;
    }
    int b = lo;
    int rem = s - sP4[b];
    int L = NFEAT - b;
    int o = rem / L;
    int coff = rem % L;
    int pos = s;

    unsigned long long ov[4] = {0, 0, 0, 0};        // 8 rows as 4x f32x2
    const ulonglong2* xs2 = (const ulonglong2*)xs;  // 64 16B-quads per feature

    while (pos < e) {
        L = NFEAT - b;
        int a0 = o << 2;
        int na = b + 1 - a0;
        if (na > 4) na = 4;
        int seg = L - coff;
        if (seg > e - pos) seg = e - pos;

        // stream weight base for this lane's staging stream
        int aj = (st < na) ? (a0 + st) : a0;        // dead streams alias 0
        const float* wstream = w + comb_base(aj, b) + coff;
        int maxi = L - 1 - coff;                    // max valid step offset

        unsigned long long acc[4][4];
#pragma unroll
        for (int j = 0; j < 4; j++) {
            acc[j][0] = 0; acc[j][1] = 0; acc[j][2] = 0; acc[j][3] = 0;
        }

        const ulonglong2* xp = xs2 + (size_t)(b + coff) * 64 + lane;

        // one c-step: broadcast LDS.128 of 4 streams' weights + 2 x-quads
        auto consume = [&](const float* cur, int u) {
            float4 w4 = ((const float4*)cur)[u];
            ulonglong2 x0 = xp[0];
            ulonglong2 x1 = xp[32];
            xp += 64;
            unsigned long long w2;
            w2 = pack2(w4.x);
            fma2(acc[0][0], w2, x0.x); fma2(acc[0][1], w2, x0.y);
            fma2(acc[0][2], w2, x1.x); fma2(acc[0][3], w2, x1.y);
            w2 = pack2(w4.y);
            fma2(acc[1][0], w2, x0.x); fma2(acc[1][1], w2, x0.y);
            fma2(acc[1][2], w2, x1.x); fma2(acc[1][3], w2, x1.y);
            w2 = pack2(w4.z);
            fma2(acc[2][0], w2, x0.x); fma2(acc[2][1], w2, x0.y);
            fma2(acc[2][2], w2, x1.x); fma2(acc[2][3], w2, x1.y);
            w2 = pack2(w4.w);
            fma2(acc[3][0], w2, x0.x); fma2(acc[3][1], w2, x0.y);
            fma2(acc[3][2], w2, x1.x); fma2(acc[3][3], w2, x1.y);
        };

        // ---- stage group 0 ----
        {
            int idx = u8;
            if (idx > maxi) idx = maxi;
            wsw[u8 * 4 + st] = __ldg(wstream + idx);
        }
        __syncwarp();

        int nG = (seg + 7) >> 3;
        for (int g = 0; g < nG; g++) {
            float fn = 0.0f;
            bool more = (g + 1) < nG;
            if (more) {                   // prefetch next group (in-bounds clamp)
                int idx = 8 * (g + 1) + u8;
                if (idx > maxi) idx = maxi;
                fn = __ldg(wstream + idx);
            }
            const float* cur = wsw + (g & 1) * 32;
            int n = seg - 8 * g;
            if (n >= 8) {
#pragma unroll
                for (int u = 0; u < 8; u++) consume(cur, u);
            } else {
#pragma unroll
                for (int u = 0; u < 8; u++)
                    if (u < n) consume(cur, u);
            }
            if (more) {
                wsw[((g + 1) & 1) * 32 + u8 * 4 + st] = fn;
                __syncwarp();
            }
        }

        // epilogue: out += (x_a * x_b) * s_ab  (linearity allows partial runs)
        {
            const ulonglong2* xbp = xs2 + (size_t)b * 64 + lane;
            ulonglong2 xb0 = xbp[0];
            ulonglong2 xb1 = xbp[32];
#pragma unroll
            for (int j = 0; j < 4; j++) {
                if (j < na) {
                    const ulonglong2* xap = xs2 + (size_t)(a0 + j) * 64 + lane;
                    ulonglong2 xa0 = xap[0];
                    ulonglong2 xa1 = xap[32];
                    fma2(ov[0], mul2(xa0.x, xb0.x), acc[j][0]);
                    fma2(ov[1], mul2(xa0.y, xb0.y), acc[j][1]);
                    fma2(ov[2], mul2(xa1.x, xb1.x), acc[j][2]);
                    fma2(ov[3], mul2(xa1.y, xb1.y), acc[j][3]);
                }
            }
        }

        pos += seg;
        coff += seg;
        if (coff == L) {
            coff = 0;
            o++;
            if ((o << 2) > b) { o = 0; b++; }
        }
    }

    // ---- per-warp partials -> smem, block combine -> global partial ----
    {
        float4* ob = (float4*)(obuf + warp * NROW);
        union { unsigned long long q[2]; float4 f; } u;
        u.q[0] = ov[0]; u.q[1] = ov[1];
        ob[lane] = u.f;                   // rows 4*lane .. 4*lane+3
        u.q[0] = ov[2]; u.q[1] = ov[3];
        ob[lane + 32] = u.f;              // rows 128+4*lane ..
    }
    __syncthreads();
    if (tid < NROW) {
        float ssum = 0.0f;
#pragma unroll
        for (int k = 0; k < WPB; k++) ssum += obuf[k * NROW + tid];
        g_partial[blockIdx.x * NROW + tid] = ssum;
    }

    // ---- fused cross-block reduction: last block reduces ----
    __threadfence();
    __syncthreads();
    if (tid == 0) is_last = (atomicAdd(&g_count, 1) == NBLK - 1);
    __syncthreads();
    if (is_last && tid < NROW) {
        __threadfence();
        float s0 = 0.f, s1 = 0.f, s2 = 0.f, s3 = 0.f;
#pragma unroll
        for (int i = 0; i < NBLK; i += 4) {
            s0 += g_partial[(i + 0) * NROW + tid];
            s1 += g_partial[(i + 1) * NROW + tid];
            s2 += g_partial[(i + 2) * NROW + tid];
            s3 += g_partial[(i + 3) * NROW + tid];
        }
        out[tid] = (s0 + s1) + (s2 + s3);
        if (tid == 0) g_count = 0;        // reset for next graph replay
    }
}

extern "C" void kernel_launch(void* const* d_in, const int* in_sizes, int n_in,
                              void* d_out, int out_size) {
    (void)in_sizes; (void)n_in; (void)out_size;
    const float* x = (const float*)d_in[0];
    const float* w = (const float*)d_in[1];
    // d_in[2] (comb_idx) intentionally unused: lexicographic rank is closed-form.

    size_t smem_bytes =
        (size_t)(NFEAT * NROW + WPB * NROW + WPB * 64) * sizeof(float);  // 152,576 B
    cudaFuncSetAttribute(honu_main, cudaFuncAttributeMaxDynamicSharedMemorySize,
                         (int)smem_bytes);
    honu_main<<<NBLK, 512, smem_bytes>>>(x, w, (float*)d_out);
}

// round 14
// speedup vs baseline: 1.1957x; 1.1957x over previous
#include <cuda_runtime.h>

// HONU degree-3: out[r] = sum_{a<=b<=c} w(a,b,c) * xs[a][r]*xs[b][r]*xs[c][r]
// xs[0][r]=1 (bias). Weight index = lexicographic rank (closed form); the
// comb_idx input is redundant and ignored.
//
// Pair factorization: s_ab[r] = sum_c w_abc * xs[c][r];
//                     out[r] += xs[a][r]*xs[b][r]*s_ab[r].
// Main loop = R10 (best measured: 32.9us): FOUR 'a'-streams share each xs[c]
// LDS.128; warp owns all 256 rows (8 rows/thread = 4x packed fma.rn.f32x2),
// unroll-2 front-loaded uniform weight LDGs. Grid=148 (1 wave), 512 thr.
// NEW vs R10: the serialized single-block tail reduction (measured 15.5us
// standalone in R1; ~5-8us fused) is replaced by a fully parallel second
// kernel: one block PER ROW, 128 threads, 1-2 loads each + tree reduce.

#define NFEAT 129
#define NROW  256
#define NBLK  148
#define WPB   16
#define NRANGE (NBLK * WPB)   // 2368 ranges, one warp each (full 256 rows)

__host__ __device__ __forceinline__ int c2i(int v) { return v * (v - 1) / 2; }
__host__ __device__ __forceinline__ int c3i(int v) { return v * (v - 1) * (v - 2) / 6; }

// flat lexicographic rank of combo (a, b, b); total combos = C(131,3) = 366145
__device__ __forceinline__ int comb_base(int a, int b) {
    return 366145 - c3i(131 - a) + c2i(130 - a) - c2i(130 - b);
}

// total c-steps over all (b, quartet) rows: sum_b (b/4+1)*(129-b)
constexpr int t4_calc() {
    int t = 0;
    for (int b = 0; b < NFEAT; b++) t += (b / 4 + 1) * (NFEAT - b);
    return t;
}
constexpr int T4 = t4_calc();

__device__ float g_partial[NBLK * NROW];

__device__ __forceinline__ unsigned long long pack2(float w) {
    unsigned long long r;
    unsigned int wi = __float_as_uint(w);
    asm("mov.b64 %0, {%1, %1};" : "=l"(r) : "r"(wi));
    return r;
}
__device__ __forceinline__ void fma2(unsigned long long& d, unsigned long long a,
                                     unsigned long long b) {
    asm("fma.rn.f32x2 %0, %1, %2, %0;" : "+l"(d) : "l"(a), "l"(b));
}
__device__ __forceinline__ unsigned long long mul2(unsigned long long a,
                                                   unsigned long long b) {
    unsigned long long d;
    asm("mul.rn.f32x2 %0, %1, %2;" : "=l"(d) : "l"(a), "l"(b));
    return d;
}

__global__ void __launch_bounds__(512, 1)
honu_main(const float* __restrict__ x, const float* __restrict__ w) {
    extern __shared__ float smem[];
    float* xs   = smem;                   // [129][256] feature-major
    float* obuf = smem + NFEAT * NROW;    // [16][256] per-warp partials
    __shared__ int sP4[130];              // prefix of c-steps before feature b

    int tid = threadIdx.x;

    // ---- prefix table ----
    if (tid < 130) {
        int p = 0;
        for (int bb = 0; bb < tid && bb < NFEAT; bb++)
            p += (bb / 4 + 1) * (NFEAT - bb);
        sP4[tid] = p;                     // sP4[129] == T4
    }

    // ---- x transposed into smem (both 256-thread halves do 64 features) ----
    {
        int r = tid & 255, h = tid >> 8;
        const float4* xg = (const float4*)(x + (size_t)r * 128 + h * 64);
#pragma unroll
        for (int k = 0; k < 16; k++) {
            float4 v = xg[k];
            int f = h * 64 + 4 * k;
            xs[(f + 1) * NROW + r] = v.x;
            xs[(f + 2) * NROW + r] = v.y;
            xs[(f + 3) * NROW + r] = v.z;
            xs[(f + 4) * NROW + r] = v.w;
        }
        if (h == 0) xs[r] = 1.0f;         // bias feature
    }
    __syncthreads();

    int warp = tid >> 5, lane = tid & 31;
    int range = blockIdx.x * WPB + warp;

    int s = (int)(((long long)T4 * range) / NRANGE);
    int e = (int)(((long long)T4 * (range + 1)) / NRANGE);

    // ---- decode start -> (b, quartet o, c-offset) via binary search ----
    int lo = 0, hi = NFEAT - 1;
    while (lo < hi) {                     // largest b with sP4[b] <= s
        int mid = (lo + hi + 1) >> 1;
        if (sP4[mid] <= s) lo = mid; else hi = mid - 1;
    }
    int b = lo;
    int rem = s - sP4[b];
    int L = NFEAT - b;
    int o = rem / L;
    int coff = rem % L;
    int pos = s;

    unsigned long long ov[4] = {0, 0, 0, 0};      // 8 rows as 4x f32x2

    const ulonglong2* xs2 = (const ulonglong2*)xs;  // 64 16B-quads per feature

    while (pos < e) {
        L = NFEAT - b;
        int a0 = o << 2;
        int na = b + 1 - a0;
        if (na > 4) na = 4;
        int seg = L - coff;
        if (seg > e - pos) seg = e - pos;

        const float* wp[4];
#pragma unroll
        for (int j = 0; j < 4; j++) {
            int aj = (j < na) ? (a0 + j) : a0;   // dead streams alias stream 0
            wp[j] = w + comb_base(aj, b) + coff;
        }

        unsigned long long acc[4][4];
#pragma unroll
        for (int j = 0; j < 4; j++) {
            acc[j][0] = 0; acc[j][1] = 0; acc[j][2] = 0; acc[j][3] = 0;
        }

        const ulonglong2* xp = xs2 + (size_t)(b + coff) * 64 + lane;

        int q = 0;
        for (; q + 2 <= seg; q += 2) {
            float wa[4], wb[4];                  // front-loaded: 8 LDGs in flight
#pragma unroll
            for (int j = 0; j < 4; j++) {
                wa[j] = __ldg(wp[j] + q);
                wb[j] = __ldg(wp[j] + q + 1);
            }
            ulonglong2 x0 = xp[0];               // rows 0-127  (feature b+coff+q)
            ulonglong2 x1 = xp[32];              // rows 128-255
#pragma unroll
            for (int j = 0; j < 4; j++) {
                unsigned long long w2 = pack2(wa[j]);
                fma2(acc[j][0], w2, x0.x);
                fma2(acc[j][1], w2, x0.y);
                fma2(acc[j][2], w2, x1.x);
                fma2(acc[j][3], w2, x1.y);
            }
            ulonglong2 x2 = xp[64];              // feature +1
            ulonglong2 x3 = xp[96];
#pragma unroll
            for (int j = 0; j < 4; j++) {
                unsigned long long w2 = pack2(wb[j]);
                fma2(acc[j][0], w2, x2.x);
                fma2(acc[j][1], w2, x2.y);
                fma2(acc[j][2], w2, x3.x);
                fma2(acc[j][3], w2, x3.y);
            }
            xp += 128;
        }
        if (q < seg) {                            // odd tail step
            ulonglong2 x0 = xp[0];
            ulonglong2 x1 = xp[32];
#pragma unroll
            for (int j = 0; j < 4; j++) {
                unsigned long long w2 = pack2(__ldg(wp[j] + q));
                fma2(acc[j][0], w2, x0.x);
                fma2(acc[j][1], w2, x0.y);
                fma2(acc[j][2], w2, x1.x);
                fma2(acc[j][3], w2, x1.y);
            }
        }

        // epilogue: out += (x_a * x_b) * s_ab  (linearity allows partial runs)
        {
            const ulonglong2* xbp = xs2 + (size_t)b * 64 + lane;
            ulonglong2 xb0 = xbp[0];
            ulonglong2 xb1 = xbp[32];
#pragma unroll
            for (int j = 0; j < 4; j++) {
                if (j < na) {
                    const ulonglong2* xap = xs2 + (size_t)(a0 + j) * 64 + lane;
                    ulonglong2 xa0 = xap[0];
                    ulonglong2 xa1 = xap[32];
                    fma2(ov[0], mul2(xa0.x, xb0.x), acc[j][0]);
                    fma2(ov[1], mul2(xa0.y, xb0.y), acc[j][1]);
                    fma2(ov[2], mul2(xa1.x, xb1.x), acc[j][2]);
                    fma2(ov[3], mul2(xa1.y, xb1.y), acc[j][3]);
                }
            }
        }

        pos += seg;
        coff += seg;
        if (coff == L) {
            coff = 0;
            o++;
            if ((o << 2) > b) { o = 0; b++; }
        }
    }

    // ---- per-warp partials -> smem, block combine -> global partial ----
    {
        float4* ob = (float4*)(obuf + warp * NROW);
        union { unsigned long long q[2]; float4 f; } u;
        u.q[0] = ov[0]; u.q[1] = ov[1];
        ob[lane] = u.f;                   // rows 4*lane .. 4*lane+3
        u.q[0] = ov[2]; u.q[1] = ov[3];
        ob[lane + 32] = u.f;              // rows 128+4*lane ..
    }
    __syncthreads();
    if (tid < NROW) {
        float ssum = 0.0f;
#pragma unroll
        for (int k = 0; k < WPB; k++) ssum += obuf[k * NROW + tid];
        g_partial[blockIdx.x * NROW + tid] = ssum;
    }
}

// One block per row; 128 threads; each thread sums ceil(148/128)=2 partials,
// then warp-shuffle + smem tree reduce. Fully parallel: ~600 cycles.
__global__ void __launch_bounds__(128, 8)
honu_reduce(float* __restrict__ out) {
    __shared__ float wsum[4];
    int r = blockIdx.x;                   // row
    int tid = threadIdx.x;

    float v = 0.0f;
    if (tid < NBLK) v = g_partial[tid * NROW + r];
    if (tid + 128 < NBLK) v += g_partial[(tid + 128) * NROW + r];

#pragma unroll
    for (int d = 16; d > 0; d >>= 1)
        v += __shfl_down_sync(0xFFFFFFFFu, v, d);
    if ((tid & 31) == 0) wsum[tid >> 5] = v;
    __syncthreads();
    if (tid == 0)
        out[r] = (wsum[0] + wsum[1]) + (wsum[2] + wsum[3]);
}

extern "C" void kernel_launch(void* const* d_in, const int* in_sizes, int n_in,
                              void* d_out, int out_size) {
    (void)in_sizes; (void)n_in; (void)out_size;
    const float* x = (const float*)d_in[0];
    const float* w = (const float*)d_in[1];
    // d_in[2] (comb_idx) intentionally unused: lexicographic rank is closed-form.

    size_t smem_bytes = (size_t)(NFEAT * NROW + WPB * NROW) * sizeof(float);  // 148,480 B
    cudaFuncSetAttribute(honu_main, cudaFuncAttributeMaxDynamicSharedMemorySize,
                         (int)smem_bytes);
    honu_main<<<NBLK, 512, smem_bytes>>>(x, w);
    honu_reduce<<<NROW, 128>>>((float*)d_out);
}